// round 1
// baseline (speedup 1.0000x reference)
#include <cuda_runtime.h>

// Problem constants: B=4, L=4, N=2048, H=64, V=4, label_plus1=5
#define B_    4
#define L_    4
#define N_    2048
#define H_    64

// Scratch (device globals; no allocation allowed)
__device__ float d_h[B_ * N_ * H_];            // 2 MB: tanh(LN(fc(x,feat)))
__device__ float d_g[B_ * 5 * N_ * H_];        // 10 MB: g_j = h @ M_j (j=0..4), M prescaled by 1/5
__device__ float d_M[5 * H_ * H_];             // M[l,d,e] = sum_v a[l,v] W[d,v,e] / 5

// ---------------------------------------------------------------------------
// Kernel 1: M = (a @ W) / 5.  [5,64,64], each element = 4 MACs.
// ---------------------------------------------------------------------------
__global__ void k_M(const float* __restrict__ W, const float* __restrict__ a) {
    int idx = blockIdx.x * 256 + threadIdx.x;
    if (idx >= 5 * 64 * 64) return;
    int e = idx & 63, d = (idx >> 6) & 63, l = idx >> 12;
    float s = 0.f;
#pragma unroll
    for (int v = 0; v < 4; v++) s += a[l * 4 + v] * W[(d * 4 + v) * 64 + e];
    d_M[idx] = s * 0.2f;
}

// ---------------------------------------------------------------------------
// Kernel 2: h = tanh(LayerNorm(concat(x,feat) @ fc_w^T + fc_b))
// One warp per row (8192 rows). Each lane computes outputs e=lane, lane+32.
// ---------------------------------------------------------------------------
__global__ void k_h(const float* __restrict__ x, const float* __restrict__ feat,
                    const float* __restrict__ fcw, const float* __restrict__ fcb,
                    const float* __restrict__ lng, const float* __restrict__ lnb) {
    __shared__ float sw[64 * 66];
    __shared__ float sp[3][64];
    __shared__ float srow[8][68];
    int tid = threadIdx.x;
    for (int i = tid; i < 64 * 66; i += 256) sw[i] = fcw[i];
    if (tid < 64) { sp[0][tid] = fcb[tid]; sp[1][tid] = lng[tid]; sp[2][tid] = lnb[tid]; }
    int warp = tid >> 5, lane = tid & 31;
    int row = blockIdx.x * 8 + warp;               // 0..8191
    srow[warp][lane]      = x[row * 64 + lane];
    srow[warp][lane + 32] = x[row * 64 + lane + 32];
    if (lane < 2) srow[warp][64 + lane] = feat[row * 2 + lane];
    __syncthreads();

    float h0 = sp[0][lane], h1 = sp[0][lane + 32];
#pragma unroll
    for (int k = 0; k < 66; k++) {
        float xk = srow[warp][k];
        h0 += sw[lane * 66 + k] * xk;
        h1 += sw[(lane + 32) * 66 + k] * xk;
    }
    // LayerNorm over 64 values (2 per lane)
    float s = h0 + h1, sq = h0 * h0 + h1 * h1;
#pragma unroll
    for (int o = 16; o > 0; o >>= 1) {
        s  += __shfl_xor_sync(0xffffffff, s,  o);
        sq += __shfl_xor_sync(0xffffffff, sq, o);
    }
    float mu  = s * (1.f / 64.f);
    float var = sq * (1.f / 64.f) - mu * mu;
    float inv = rsqrtf(var + 1e-5f);
    h0 = tanhf((h0 - mu) * inv * sp[1][lane]      + sp[2][lane]);
    h1 = tanhf((h1 - mu) * inv * sp[1][lane + 32] + sp[2][lane + 32]);
    d_h[row * 64 + lane]      = h0;
    d_h[row * 64 + lane + 32] = h1;
}

// ---------------------------------------------------------------------------
// Kernel 3: g[b,j,n,:] = h[b,n,:] @ M[j]   for j = 0..4  (M prescaled by 1/5)
// Grid (128 row-tiles of 64, 5 j). 256 threads: 4 threads/row, 16 cols each.
// ---------------------------------------------------------------------------
__global__ void k_g() {
    __shared__ float Ms[64][64];
    __shared__ float hs[64][65];
    int tid = threadIdx.x;
    int j = blockIdx.y;
    int row0 = blockIdx.x * 64;
    for (int i = tid; i < 4096; i += 256) Ms[i >> 6][i & 63] = d_M[j * 4096 + i];
    for (int i = tid; i < 4096; i += 256) hs[i >> 6][i & 63] = d_h[row0 * 64 + i];
    __syncthreads();
    int r  = tid >> 2;          // 0..63
    int c0 = (tid & 3) * 16;
    float acc[16];
#pragma unroll
    for (int c = 0; c < 16; c++) acc[c] = 0.f;
#pragma unroll 8
    for (int d = 0; d < 64; d++) {
        float hv = hs[r][d];
#pragma unroll
        for (int c = 0; c < 16; c++) acc[c] += hv * Ms[d][c0 + c];
    }
    int grow = row0 + r;
    int b = grow >> 11, n = grow & 2047;
    float* dst = d_g + (((size_t)(b * 5 + j) * N_ + n) * 64 + c0);
#pragma unroll
    for (int c = 0; c < 16; c++) dst[c] = acc[c];
}

// ---------------------------------------------------------------------------
// Kernel 4 (dominant): out[b,n,:] = x + g0 + sum_l adj[b,l,n,:] @ g_{l+1}
// Per (b, 64-row tile): C[64,64], K = 4*2048 reduction. fp32 via fma.rn.f32x2.
// Thread tile 2 rows x 8 cols, 256 threads, KT=32, register-staged dbl buffer.
// ---------------------------------------------------------------------------
__global__ __launch_bounds__(256) void k_main(const float* __restrict__ adj,
                                              const float* __restrict__ x,
                                              float* __restrict__ out) {
    __shared__ __align__(16) float As[64][36];   // adj tile, padded
    __shared__ __align__(16) float Bs[32][68];   // g tile, padded (16B-friendly)

    int tid = threadIdx.x;
    int b   = blockIdx.y;
    int n0  = blockIdx.x * 64;

    // loader mapping
    int arow = tid >> 3, acol = (tid & 7) * 4;    // adj: rows arow, arow+32; 4 cols
    int grow = tid >> 4, gcol = (tid & 15) * 4;   // g:   rows grow, grow+16; 4 cols

    // compute mapping: 2 rows x 8 cols per thread
    int ty = tid >> 3;          // 0..31 -> rows {2ty, 2ty+1}
    int tx = tid & 7;           // cols tx*8 .. tx*8+7

    const float* adjb = adj + (size_t)b * L_ * N_ * N_;

    // acc as packed f32x2 pairs, init = x + g0
    unsigned long long acc[2][4];
#pragma unroll
    for (int r = 0; r < 2; r++) {
        int gn = n0 + 2 * ty + r;
        const float* g0p = d_g + ((size_t)(b * 5) * N_ + gn) * 64 + tx * 8;
        const float* xp  = x   + ((size_t)b * N_ + gn) * 64 + tx * 8;
#pragma unroll
        for (int j = 0; j < 4; j++) {
            float lo = g0p[2 * j]     + xp[2 * j];
            float hi = g0p[2 * j + 1] + xp[2 * j + 1];
            asm("mov.b64 %0, {%1, %2};" : "=l"(acc[r][j])
                : "r"(__float_as_uint(lo)), "r"(__float_as_uint(hi)));
        }
    }

    float4 ra0, ra1, rb0, rb1;
    // prefetch tile 0 (l=0, m0=0)
    {
        const float* ap = adjb + ((size_t)(n0 + arow)) * N_ + acol;
        ra0 = *(const float4*)ap;
        ra1 = *(const float4*)(ap + (size_t)32 * N_);
        const float* gp = d_g + ((size_t)(b * 5 + 1) * N_ + grow) * 64 + gcol;
        rb0 = *(const float4*)gp;
        rb1 = *(const float4*)(gp + 16 * 64);
    }

    for (int t = 0; t < 256; t++) {               // 4 l * 64 k-tiles
        // stage registers -> smem
        As[arow][acol + 0] = ra0.x; As[arow][acol + 1] = ra0.y;
        As[arow][acol + 2] = ra0.z; As[arow][acol + 3] = ra0.w;
        As[arow + 32][acol + 0] = ra1.x; As[arow + 32][acol + 1] = ra1.y;
        As[arow + 32][acol + 2] = ra1.z; As[arow + 32][acol + 3] = ra1.w;
        Bs[grow][gcol + 0] = rb0.x; Bs[grow][gcol + 1] = rb0.y;
        Bs[grow][gcol + 2] = rb0.z; Bs[grow][gcol + 3] = rb0.w;
        Bs[grow + 16][gcol + 0] = rb1.x; Bs[grow + 16][gcol + 1] = rb1.y;
        Bs[grow + 16][gcol + 2] = rb1.z; Bs[grow + 16][gcol + 3] = rb1.w;
        __syncthreads();

        int tn = t + 1;
        if (tn < 256) {                            // prefetch next tile
            int l = tn >> 6, m0 = (tn & 63) * 32;
            const float* ap = adjb + ((size_t)l * N_ + n0 + arow) * N_ + m0 + acol;
            ra0 = *(const float4*)ap;
            ra1 = *(const float4*)(ap + (size_t)32 * N_);
            const float* gp = d_g + ((size_t)(b * 5 + l + 1) * N_ + m0 + grow) * 64 + gcol;
            rb0 = *(const float4*)gp;
            rb1 = *(const float4*)(gp + 16 * 64);
        }

#pragma unroll
        for (int k = 0; k < 32; k++) {
            float a0f = As[2 * ty][k];
            float a1f = As[2 * ty + 1][k];
            unsigned long long aa0, aa1;
            asm("mov.b64 %0, {%1, %1};" : "=l"(aa0) : "r"(__float_as_uint(a0f)));
            asm("mov.b64 %0, {%1, %1};" : "=l"(aa1) : "r"(__float_as_uint(a1f)));
            double2 q0 = *(const double2*)&Bs[k][tx * 8];       // pre-packed f32x2 pairs
            double2 q1 = *(const double2*)&Bs[k][tx * 8 + 4];
            unsigned long long bv0 = __double_as_longlong(q0.x);
            unsigned long long bv1 = __double_as_longlong(q0.y);
            unsigned long long bv2 = __double_as_longlong(q1.x);
            unsigned long long bv3 = __double_as_longlong(q1.y);
            asm("fma.rn.f32x2 %0, %1, %2, %0;" : "+l"(acc[0][0]) : "l"(aa0), "l"(bv0));
            asm("fma.rn.f32x2 %0, %1, %2, %0;" : "+l"(acc[0][1]) : "l"(aa0), "l"(bv1));
            asm("fma.rn.f32x2 %0, %1, %2, %0;" : "+l"(acc[0][2]) : "l"(aa0), "l"(bv2));
            asm("fma.rn.f32x2 %0, %1, %2, %0;" : "+l"(acc[0][3]) : "l"(aa0), "l"(bv3));
            asm("fma.rn.f32x2 %0, %1, %2, %0;" : "+l"(acc[1][0]) : "l"(aa1), "l"(bv0));
            asm("fma.rn.f32x2 %0, %1, %2, %0;" : "+l"(acc[1][1]) : "l"(aa1), "l"(bv1));
            asm("fma.rn.f32x2 %0, %1, %2, %0;" : "+l"(acc[1][2]) : "l"(aa1), "l"(bv2));
            asm("fma.rn.f32x2 %0, %1, %2, %0;" : "+l"(acc[1][3]) : "l"(aa1), "l"(bv3));
        }
        __syncthreads();
    }

    // write out
#pragma unroll
    for (int r = 0; r < 2; r++) {
        int gn = n0 + 2 * ty + r;
        unsigned long long* op =
            (unsigned long long*)(out + ((size_t)b * N_ + gn) * 64 + tx * 8);
#pragma unroll
        for (int j = 0; j < 4; j++) op[j] = acc[r][j];
    }
}

// ---------------------------------------------------------------------------
// Launch: x, feature, adj, fc_w, fc_b, ln_g, ln_b, W, a  (metadata order)
// ---------------------------------------------------------------------------
extern "C" void kernel_launch(void* const* d_in, const int* in_sizes, int n_in,
                              void* d_out, int out_size) {
    const float* x    = (const float*)d_in[0];
    const float* feat = (const float*)d_in[1];
    const float* adj  = (const float*)d_in[2];
    const float* fcw  = (const float*)d_in[3];
    const float* fcb  = (const float*)d_in[4];
    const float* lng  = (const float*)d_in[5];
    const float* lnb  = (const float*)d_in[6];
    const float* W    = (const float*)d_in[7];
    const float* a    = (const float*)d_in[8];
    float* out = (float*)d_out;

    k_M<<<80, 256>>>(W, a);
    k_h<<<1024, 256>>>(x, feat, fcw, fcb, lng, lnb);
    k_g<<<dim3(128, 5), 256>>>();
    k_main<<<dim3(32, 4), 256>>>(adj, x, out);
}

// round 3
// speedup vs baseline: 3.7379x; 3.7379x over previous
#include <cuda_runtime.h>
#include <cuda_fp16.h>
#include <cstdint>

// Problem constants: B=4, L=4, N=2048, H=64, V=4, label_plus1=5
#define B_    4
#define L_    4
#define N_    2048
#define H_    64

// Pipeline config for k_main
#define STAGES      9
#define A_ST        16384              // 128 rows x 32 k x 4B (SW128 swizzled)
#define B_ST        5120               // 64 rows x 80B (32 k fp16 + 16B pad)
#define STAGE_BYTES (A_ST + B_ST)      // 21504
#define SMEM_TOTAL  (STAGES * STAGE_BYTES)

// Scratch (device globals; no allocation allowed)
__device__ float  d_h [B_ * N_ * H_];        // 2 MB
__device__ float  d_g0[B_ * N_ * H_];        // 2 MB: identity-label term (h @ M0)/5
__device__ __half d_gt[B_ * 4 * H_ * N_];    // 4 MB: g_{l+1} transposed [b,l,e,m], fp16
__device__ float  d_M [5 * H_ * H_];

// ---------------------------------------------------------------------------
// Helpers
// ---------------------------------------------------------------------------
__device__ __forceinline__ uint32_t smem_u32(const void* p) {
    uint32_t a;
    asm("{ .reg .u64 t; cvta.to.shared.u64 t, %1; cvt.u32.u64 %0, t; }" : "=r"(a) : "l"(p));
    return a;
}
#define SWZ(o) ((o) ^ (((o) >> 3) & 0x70))

__device__ __forceinline__ void cpasync16(uint32_t saddr, const void* gaddr) {
    asm volatile("cp.async.cg.shared.global [%0], [%1], 16;" :: "r"(saddr), "l"(gaddr));
}
__device__ __forceinline__ void lds_v2(float& x, float& y, uint32_t a) {
    asm volatile("ld.shared.v2.f32 {%0, %1}, [%2];" : "=f"(x), "=f"(y) : "r"(a));
}
__device__ __forceinline__ uint32_t lds_b32(uint32_t a) {
    uint32_t v;
    asm volatile("ld.shared.b32 %0, [%1];" : "=r"(v) : "r"(a));
    return v;
}
__device__ __forceinline__ uint32_t cvt_h2(float hi, float lo) {   // {lo, hi} packed
    uint32_t r;
    asm("cvt.rn.f16x2.f32 %0, %1, %2;" : "=r"(r) : "f"(hi), "f"(lo));
    return r;
}
__device__ __forceinline__ void mma16816(float* c, const uint32_t* a, uint32_t b0, uint32_t b1) {
    asm volatile(
        "mma.sync.aligned.m16n8k16.row.col.f32.f16.f16.f32 "
        "{%0,%1,%2,%3}, {%4,%5,%6,%7}, {%8,%9}, {%0,%1,%2,%3};"
        : "+f"(c[0]), "+f"(c[1]), "+f"(c[2]), "+f"(c[3])
        : "r"(a[0]), "r"(a[1]), "r"(a[2]), "r"(a[3]), "r"(b0), "r"(b1));
}

// ---------------------------------------------------------------------------
// Kernel 1: M = (a @ W) / 5
// ---------------------------------------------------------------------------
__global__ void k_M(const float* __restrict__ W, const float* __restrict__ a) {
    int idx = blockIdx.x * 256 + threadIdx.x;
    if (idx >= 5 * 64 * 64) return;
    int e = idx & 63, d = (idx >> 6) & 63, l = idx >> 12;
    float s = 0.f;
#pragma unroll
    for (int v = 0; v < 4; v++) s += a[l * 4 + v] * W[(d * 4 + v) * 64 + e];
    d_M[idx] = s * 0.2f;
}

// ---------------------------------------------------------------------------
// Kernel 2: h = tanh(LayerNorm(concat(x,feat) @ fc_w^T + fc_b))
// ---------------------------------------------------------------------------
__global__ void k_h(const float* __restrict__ x, const float* __restrict__ feat,
                    const float* __restrict__ fcw, const float* __restrict__ fcb,
                    const float* __restrict__ lng, const float* __restrict__ lnb) {
    __shared__ float sw[64 * 66];
    __shared__ float sp[3][64];
    __shared__ float srow[8][68];
    int tid = threadIdx.x;
    for (int i = tid; i < 64 * 66; i += 256) sw[i] = fcw[i];
    if (tid < 64) { sp[0][tid] = fcb[tid]; sp[1][tid] = lng[tid]; sp[2][tid] = lnb[tid]; }
    int warp = tid >> 5, lane = tid & 31;
    int row = blockIdx.x * 8 + warp;
    srow[warp][lane]      = x[row * 64 + lane];
    srow[warp][lane + 32] = x[row * 64 + lane + 32];
    if (lane < 2) srow[warp][64 + lane] = feat[row * 2 + lane];
    __syncthreads();

    float h0 = sp[0][lane], h1 = sp[0][lane + 32];
#pragma unroll
    for (int k = 0; k < 66; k++) {
        float xk = srow[warp][k];
        h0 += sw[lane * 66 + k] * xk;
        h1 += sw[(lane + 32) * 66 + k] * xk;
    }
    float s = h0 + h1, sq = h0 * h0 + h1 * h1;
#pragma unroll
    for (int o = 16; o > 0; o >>= 1) {
        s  += __shfl_xor_sync(0xffffffff, s,  o);
        sq += __shfl_xor_sync(0xffffffff, sq, o);
    }
    float mu  = s * (1.f / 64.f);
    float var = sq * (1.f / 64.f) - mu * mu;
    float inv = rsqrtf(var + 1e-5f);
    h0 = tanhf((h0 - mu) * inv * sp[1][lane]      + sp[2][lane]);
    h1 = tanhf((h1 - mu) * inv * sp[1][lane + 32] + sp[2][lane + 32]);
    d_h[row * 64 + lane]      = h0;
    d_h[row * 64 + lane + 32] = h1;
}

// ---------------------------------------------------------------------------
// Kernel 3: g_j = h @ M_j.  Grid (128 row-tiles, 5 j).
// j=0 -> d_g0 [b,n,e] fp32; j>=1 -> d_gt [b,j-1,e,m] fp16 (transposed, K-major)
// ---------------------------------------------------------------------------
__global__ void k_g() {
    __shared__ float Ms[64][65];    // reused as transpose buffer after compute
    __shared__ float hs[64][65];
    int tid = threadIdx.x;
    int j = blockIdx.y;
    int row0 = blockIdx.x * 64;
    int b = row0 >> 11, nn0 = row0 & 2047;
    for (int i = tid; i < 4096; i += 256) {
        hs[i >> 6][i & 63] = d_h[(size_t)row0 * 64 + i];
        Ms[i >> 6][i & 63] = d_M[j * 4096 + i];
    }
    __syncthreads();
    int r = tid >> 2, c0 = (tid & 3) * 16;
    float acc[16];
#pragma unroll
    for (int c = 0; c < 16; c++) acc[c] = 0.f;
#pragma unroll 8
    for (int d = 0; d < 64; d++) {
        float hv = hs[r][d];
#pragma unroll
        for (int c = 0; c < 16; c++) acc[c] += hv * Ms[d][c0 + c];
    }
    if (j == 0) {
        float* dst = d_g0 + ((size_t)row0 + r) * 64 + c0;
#pragma unroll
        for (int c = 0; c < 16; c++) dst[c] = acc[c];
    } else {
        __syncthreads();               // everyone done reading Ms
#pragma unroll
        for (int c = 0; c < 16; c++) Ms[c0 + c][r] = acc[c];   // transpose
        __syncthreads();
        int e = tid >> 2, ms = (tid & 3) * 16;
        __half2 h2[8];
#pragma unroll
        for (int q = 0; q < 8; q++)
            h2[q] = __floats2half2_rn(Ms[e][ms + 2 * q], Ms[e][ms + 2 * q + 1]);
        __half* dst = d_gt + ((size_t)(b * 4 + j - 1) * 64 + e) * 2048 + nn0 + ms;
        uint4* d4 = (uint4*)dst;
        d4[0] = *(uint4*)&h2[0];
        d4[1] = *(uint4*)&h2[4];
    }
}

// ---------------------------------------------------------------------------
// Kernel 4 (dominant): fp16 mma.sync GEMM with 9-stage cp.async pipeline.
// CTA: D[128 m-rows(nodes), 64 n-cols(e)] = sum_{l,k} adj[b,l,m,k] * g[b,l,k,e]
// A tile: 128x32 fp32 SW128 in smem (cvt to fp16 in regs).
// B tile: 64(e) x 32(k) fp16, rows padded to 80B (conflict-free).
// Warp grid 4(m) x 2(n); warp tile 32x32 -> 16 mma per 32-k stage.
// ---------------------------------------------------------------------------
__device__ __forceinline__ void load_stage(int t, int slot, uint32_t sb, int tid,
                                           const float* __restrict__ adjb,
                                           const __half* __restrict__ gtb, int n0) {
    if (t < 256) {
        int l = t >> 6, m0 = (t & 63) * 32;
        uint32_t aB = sb + slot * STAGE_BYTES;
        uint32_t bB = aB + A_ST;
        const float* asrc = adjb + ((size_t)l * N_ + n0) * N_ + m0;
#pragma unroll
        for (int i = 0; i < 4; i++) {
            int ch = tid + i * 256;           // 0..1023
            int row = ch >> 3, c16 = ch & 7;
            cpasync16(aB + SWZ(row * 128 + c16 * 16), asrc + (size_t)row * N_ + c16 * 4);
        }
        {
            int e = tid >> 2, c16 = tid & 3;  // 256 chunks
            cpasync16(bB + e * 80 + c16 * 16,
                      gtb + ((size_t)l * 64 + e) * 2048 + m0 + c16 * 8);
        }
    }
    asm volatile("cp.async.commit_group;");
}

__global__ void __launch_bounds__(256, 1)
k_main(const float* __restrict__ adj, const float* __restrict__ x,
       float* __restrict__ out) {
    extern __shared__ __align__(1024) char smem[];
    uint32_t sb = smem_u32(smem);
    int tid = threadIdx.x, wid = tid >> 5, lane = tid & 31;
    int gid = lane >> 2, tig = lane & 3;
    int b = blockIdx.y;
    int n0 = blockIdx.x * 128;
    int warp_m = wid & 3, warp_n = wid >> 2;

    const float*  adjb = adj  + (size_t)b * L_ * N_ * N_;
    const __half* gtb  = d_gt + (size_t)b * 4 * 64 * 2048;

    // Precomputed A-fragment addressing (SW128: rowxor constant across this
    // thread's rows since all rows share low 3 bits = gid&7)
    uint32_t rowxor = ((uint32_t)(gid & 7)) << 4;
    uint32_t rowoff[4];                        // [mt][half] * 128B
#pragma unroll
    for (int mt = 0; mt < 2; mt++)
#pragma unroll
        for (int h = 0; h < 2; h++)
            rowoff[mt * 2 + h] = (warp_m * 32 + mt * 16 + gid + 8 * h) * 128;
    uint32_t xk[2][2];                         // [ks][kk]
#pragma unroll
    for (int ks = 0; ks < 2; ks++)
#pragma unroll
        for (int kk = 0; kk < 2; kk++)
            xk[ks][kk] = ((uint32_t)(tig * 8 + ks * 64 + kk * 32)) ^ rowxor;
    uint32_t nb[4];                            // B row bases (80B pad)
#pragma unroll
    for (int nt = 0; nt < 4; nt++)
        nb[nt] = (warp_n * 32 + nt * 8 + gid) * 80;

    float acc[2][4][4];
#pragma unroll
    for (int mt = 0; mt < 2; mt++)
#pragma unroll
        for (int nt = 0; nt < 4; nt++)
#pragma unroll
            for (int q = 0; q < 4; q++) acc[mt][nt][q] = 0.f;

    // Prologue: stages 0..7
#pragma unroll
    for (int s = 0; s < STAGES - 1; s++) load_stage(s, s, sb, tid, adjb, gtb, n0);

#pragma unroll 1
    for (int t = 0; t < 256; t++) {
        asm volatile("cp.async.wait_group 7;");
        __syncthreads();
        int slot = t % STAGES;
        load_stage(t + STAGES - 1, (t + STAGES - 1) % STAGES, sb, tid, adjb, gtb, n0);

        uint32_t aB = sb + slot * STAGE_BYTES;
        uint32_t bB = aB + A_ST;
#pragma unroll
        for (int ks = 0; ks < 2; ks++) {
            uint32_t afr[2][4];
#pragma unroll
            for (int mt = 0; mt < 2; mt++)
#pragma unroll
                for (int kk = 0; kk < 2; kk++) {
                    float x0, x1, y0, y1;
                    lds_v2(x0, x1, aB + rowoff[mt * 2 + 0] + xk[ks][kk]);
                    lds_v2(y0, y1, aB + rowoff[mt * 2 + 1] + xk[ks][kk]);
                    afr[mt][kk * 2 + 0] = cvt_h2(x1, x0);
                    afr[mt][kk * 2 + 1] = cvt_h2(y1, y0);
                }
            uint32_t bfr[4][2];
            uint32_t kbase = (uint32_t)(tig * 4 + ks * 32);   // bytes: k0*2
#pragma unroll
            for (int nt = 0; nt < 4; nt++) {
                bfr[nt][0] = lds_b32(bB + nb[nt] + kbase);
                bfr[nt][1] = lds_b32(bB + nb[nt] + kbase + 16);
            }
#pragma unroll
            for (int mt = 0; mt < 2; mt++)
#pragma unroll
                for (int nt = 0; nt < 4; nt++)
                    mma16816(acc[mt][nt], afr[mt], bfr[nt][0], bfr[nt][1]);
        }
    }

    // Epilogue: out = acc + x + g0
#pragma unroll
    for (int mt = 0; mt < 2; mt++) {
#pragma unroll
        for (int h = 0; h < 2; h++) {
            int node = n0 + warp_m * 32 + mt * 16 + gid + 8 * h;
            size_t base = ((size_t)b * N_ + node) * 64;
#pragma unroll
            for (int nt = 0; nt < 4; nt++) {
                int col = warp_n * 32 + nt * 8 + 2 * tig;
                float2 xv = *(const float2*)(x + base + col);
                float2 gv = *(const float2*)(d_g0 + base + col);
                float2 o;
                o.x = acc[mt][nt][h * 2 + 0] + xv.x + gv.x;
                o.y = acc[mt][nt][h * 2 + 1] + xv.y + gv.y;
                *(float2*)(out + base + col) = o;
            }
        }
    }
}

// ---------------------------------------------------------------------------
// Launch: x, feature, adj, fc_w, fc_b, ln_g, ln_b, W, a
// ---------------------------------------------------------------------------
extern "C" void kernel_launch(void* const* d_in, const int* in_sizes, int n_in,
                              void* d_out, int out_size) {
    const float* x    = (const float*)d_in[0];
    const float* feat = (const float*)d_in[1];
    const float* adj  = (const float*)d_in[2];
    const float* fcw  = (const float*)d_in[3];
    const float* fcb  = (const float*)d_in[4];
    const float* lng  = (const float*)d_in[5];
    const float* lnb  = (const float*)d_in[6];
    const float* W    = (const float*)d_in[7];
    const float* a    = (const float*)d_in[8];
    float* out = (float*)d_out;

    cudaFuncSetAttribute(k_main, cudaFuncAttributeMaxDynamicSharedMemorySize, SMEM_TOTAL);

    k_M<<<80, 256>>>(W, a);
    k_h<<<1024, 256>>>(x, feat, fcw, fcb, lng, lnb);
    k_g<<<dim3(128, 5), 256>>>();
    k_main<<<dim3(16, 4), 256, SMEM_TOTAL>>>(adj, x, out);
}